// round 4
// baseline (speedup 1.0000x reference)
#include <cuda_runtime.h>
#include <cuda_bf16.h>

// ---------------------------------------------------------------------------
// ParallelTransportAttention  (B=2, S=256, D=512, H=8, Dh=64, df=32, rank=8)
// Round 4: packed fp32x2 FFMA (fma.rn.f32x2) in hol + all GEMM mainloops
// ---------------------------------------------------------------------------

__device__ __align__(256) float g_scratch[3411968];

// ---------------- packed f32x2 helpers --------------------------------------
__device__ __forceinline__ unsigned long long pk2(float x, float y) {
    unsigned long long r;
    asm("mov.b64 %0, {%1,%2};" : "=l"(r) : "f"(x), "f"(y));
    return r;
}
__device__ __forceinline__ void fma2(unsigned long long& d,
                                     unsigned long long a, unsigned long long b) {
    asm("fma.rn.f32x2 %0, %1, %2, %0;" : "+l"(d) : "l"(a), "l"(b));
}
__device__ __forceinline__ unsigned long long add2(unsigned long long a,
                                                   unsigned long long b) {
    unsigned long long r;
    asm("add.rn.f32x2 %0, %1, %2;" : "=l"(r) : "l"(a), "l"(b));
    return r;
}
__device__ __forceinline__ float2 upk2(unsigned long long v) {
    float2 f;
    asm("mov.b64 {%0,%1}, %2;" : "=f"(f.x), "=f"(f.y) : "l"(v));
    return f;
}

// ======================= 1) matrix exponential + M ==========================
__global__ __launch_bounds__(1024) void expm_kernel(
    const float* __restrict__ conn, const float* __restrict__ gen,
    float* __restrict__ Mout)
{
    __shared__ float sA[32][33], sP[32][33], sT[32][33], sW[32][33];
    __shared__ float scol[32];
    __shared__ int   s_s;
    int zs = blockIdx.x;            // 0..511
    int t  = threadIdx.x;           // 0..1023
    int a = t >> 5, b = t & 31;

    const float* c8 = conn + zs * 8;
    float acc = 0.f;
#pragma unroll
    for (int r = 0; r < 8; r++) acc += c8[r] * gen[r * 1024 + t];
    acc *= 0.1f;
    sA[a][b] = acc;
    sW[a][b] = fabsf(acc);
    __syncthreads();

    if (t < 32) {
        float cs = 0.f;
#pragma unroll
        for (int q = 0; q < 32; q++) cs += sW[q][t];
        scol[t] = cs;
    }
    __syncthreads();
    if (t == 0) {
        float nrm = 0.f;
#pragma unroll
        for (int q = 0; q < 32; q++) nrm = fmaxf(nrm, scol[q]);
        int s = 0;
        while (nrm > 0.25f * exp2f((float)s) && s < 12) s++;
        s_s = s;
    }
    __syncthreads();
    int   s  = s_s;
    float sc = exp2f((float)(-s));
    float aab = sA[a][b] * sc;
    __syncthreads();
    sA[a][b] = aab;
    sP[a][b] = aab;
    sT[a][b] = aab + ((a == b) ? 1.f : 0.f);
    __syncthreads();

    for (int k = 2; k <= 9; k++) {
        float d = 0.f;
#pragma unroll
        for (int j = 0; j < 32; j++) d += sP[a][j] * sA[j][b];
        d *= (1.f / (float)k);
        __syncthreads();
        sP[a][b] = d;
        sT[a][b] += d;
        __syncthreads();
    }
    for (int it = 0; it < s; it++) {
        float d = 0.f;
#pragma unroll
        for (int j = 0; j < 32; j++) d += sT[a][j] * sT[j][b];
        __syncthreads();
        sT[a][b] = d;
        __syncthreads();
    }
    float m = 0.f;
#pragma unroll
    for (int k2 = 0; k2 < 32; k2++) m += sT[k2][a] * sT[k2][b];
    Mout[zs * 1024 + t] = m;
}

// ======================= 2) pairwise holonomy (f32x2) =======================
// block = one (i, j-tile) of the upper triangle; warp w -> j = jt*4+w
// P = Mi*Mj computed 2 rows at a time with packed FFMA.
__global__ __launch_bounds__(128) void hol_kernel(
    const float* __restrict__ Mg, float* __restrict__ hol)
{
    __shared__ float sMi2[16][64];       // [a/2][k*2 + (a&1)] : row-pair interleave
    __shared__ float sX[4][32][34];      // sX[w][c][r] = P[r][c]
    int tlin = blockIdx.x;               // 0..8319
    int z    = blockIdx.y;
    int t = threadIdx.x;
    int w = t >> 5, lane = t & 31;

    // decode triangular tile index: C(g) = 258g - 2g^2
    int g = (int)((258.0 - sqrt(66564.0 - 8.0 * (double)tlin)) * 0.25);
    if (g > 63) g = 63;
    if (g < 0) g = 0;
    while (258 * g - 2 * g * g > tlin) g--;
    while (258 * (g + 1) - 2 * (g + 1) * (g + 1) <= tlin) g++;
    int rem = tlin - (258 * g - 2 * g * g);
    int per = 64 - g;
    int i  = 4 * g + rem / per;
    int jt = g + rem % per;

    // Mi -> interleaved smem
    const float* mi = Mg + (size_t)(z * 256 + i) * 1024;
    for (int idx = t; idx < 1024; idx += 128) {
        int a = idx >> 5, k = idx & 31;
        sMi2[a >> 1][k * 2 + (a & 1)] = mi[idx];
    }
    __syncthreads();

    int j = jt * 4 + w;
    if (j < i) return;
    if (j == i) {
        if (lane == 0) hol[((size_t)(z * 256 + i)) * 256 + i] = 0.f;
        return;
    }

    // Mj column `lane` (== row `lane`, symmetric), packed (m,m)
    unsigned long long mjp[32];
    const float4* mj4 = (const float4*)(Mg + (size_t)(z * 256 + j) * 1024 + lane * 32);
#pragma unroll
    for (int q = 0; q < 8; q++) {
        float4 v = mj4[q];
        mjp[4*q+0] = pk2(v.x, v.x);
        mjp[4*q+1] = pk2(v.y, v.y);
        mjp[4*q+2] = pk2(v.z, v.z);
        mjp[4*q+3] = pk2(v.w, v.w);
    }

    float2 p[16];
#pragma unroll
    for (int ap = 0; ap < 16; ap++) {
        unsigned long long a0 = 0, a1 = 0, a2v = 0, a3 = 0;
        const ulonglong2* row = (const ulonglong2*)&sMi2[ap][0];
#pragma unroll
        for (int k = 0; k < 32; k += 4) {
            ulonglong2 m01 = row[(k >> 1) + 0];   // pairs for k, k+1 (broadcast)
            ulonglong2 m23 = row[(k >> 1) + 1];   // pairs for k+2, k+3
            fma2(a0,  m01.x, mjp[k+0]);
            fma2(a1,  m01.y, mjp[k+1]);
            fma2(a2v, m23.x, mjp[k+2]);
            fma2(a3,  m23.y, mjp[k+3]);
        }
        unsigned long long s = add2(add2(a0, a1), add2(a2v, a3));
        p[ap] = upk2(s);                          // (P[2ap][lane], P[2ap+1][lane])
        *(float2*)&sX[w][lane][2 * ap] = p[ap];
    }
    __syncwarp();

    float t1 = sX[w][lane][lane];                 // P[lane][lane]
    float t2 = 0.f;
#pragma unroll
    for (int ap = 0; ap < 16; ap++) {
        t2 += p[ap].x * sX[w][2*ap  ][lane];      // P[2ap][lane]   * P[lane][2ap]
        t2 += p[ap].y * sX[w][2*ap+1][lane];
    }

#pragma unroll
    for (int off = 16; off; off >>= 1) {
        t1 += __shfl_down_sync(0xffffffffu, t1, off);
        t2 += __shfl_down_sync(0xffffffffu, t2, off);
    }
    if (lane == 0) {
        float h2 = t2 - 2.f * t1 + 32.f;
        float h  = sqrtf(fmaxf(h2, 0.f));
        hol[((size_t)(z * 256 + i)) * 256 + j] = h;
        hol[((size_t)(z * 256 + j)) * 256 + i] = h;
    }
}

// ======================= double-buffered 64x64 GEMM core (f32x2) ============
// As/Bs rows padded to 68 floats (16B-aligned). One sync per 32-k chunk.

#define GEMM_INNER_F32X2(cur)                                                  \
    _Pragma("unroll")                                                          \
    for (int k = 0; k < 32; k++) {                                             \
        float4 a4 = *(const float4*)&As[cur][k][ty * 4];                       \
        ulonglong2 bu = *(const ulonglong2*)&Bs[cur][k][tx * 4];               \
        unsigned long long d0 = pk2(a4.x, a4.x);                               \
        unsigned long long d1 = pk2(a4.y, a4.y);                               \
        unsigned long long d2 = pk2(a4.z, a4.z);                               \
        unsigned long long d3 = pk2(a4.w, a4.w);                               \
        fma2(acc2[0][0], d0, bu.x); fma2(acc2[0][1], d0, bu.y);                \
        fma2(acc2[1][0], d1, bu.x); fma2(acc2[1][1], d1, bu.y);                \
        fma2(acc2[2][0], d2, bu.x); fma2(acc2[2][1], d2, bu.y);                \
        fma2(acc2[3][0], d3, bu.x); fma2(acc2[3][1], d3, bu.y);                \
    }

#define GEMM_LOOP_NN(Atile, Btile, lda, ldb, NC)                               \
    {                                                                          \
        int arow = t >> 2, acol = (t & 3) * 8;                                 \
        int brow = t >> 3, bcol = (t & 7) * 8;                                 \
        float4 a0 = *(const float4*)((Atile) + (long)arow * (lda) + acol);     \
        float4 a1 = *(const float4*)((Atile) + (long)arow * (lda) + acol + 4); \
        float4 b0 = *(const float4*)((Btile) + (long)brow * (ldb) + bcol);     \
        float4 b1 = *(const float4*)((Btile) + (long)brow * (ldb) + bcol + 4); \
        As[0][acol+0][arow]=a0.x; As[0][acol+1][arow]=a0.y;                    \
        As[0][acol+2][arow]=a0.z; As[0][acol+3][arow]=a0.w;                    \
        As[0][acol+4][arow]=a1.x; As[0][acol+5][arow]=a1.y;                    \
        As[0][acol+6][arow]=a1.z; As[0][acol+7][arow]=a1.w;                    \
        *(float4*)&Bs[0][brow][bcol]   = b0;                                   \
        *(float4*)&Bs[0][brow][bcol+4] = b1;                                   \
        __syncthreads();                                                       \
        for (int c = 0; c < (NC); c++) {                                       \
            int cur = c & 1;                                                   \
            if (c + 1 < (NC)) {                                                \
                const float* Ap = (Atile) + (c + 1) * 32;                      \
                const float* Bp = (Btile) + (long)(c + 1) * 32 * (ldb);        \
                a0 = *(const float4*)(Ap + (long)arow * (lda) + acol);         \
                a1 = *(const float4*)(Ap + (long)arow * (lda) + acol + 4);     \
                b0 = *(const float4*)(Bp + (long)brow * (ldb) + bcol);         \
                b1 = *(const float4*)(Bp + (long)brow * (ldb) + bcol + 4);     \
            }                                                                  \
            GEMM_INNER_F32X2(cur)                                              \
            if (c + 1 < (NC)) {                                                \
                int nxt = cur ^ 1;                                             \
                As[nxt][acol+0][arow]=a0.x; As[nxt][acol+1][arow]=a0.y;        \
                As[nxt][acol+2][arow]=a0.z; As[nxt][acol+3][arow]=a0.w;        \
                As[nxt][acol+4][arow]=a1.x; As[nxt][acol+5][arow]=a1.y;        \
                As[nxt][acol+6][arow]=a1.z; As[nxt][acol+7][arow]=a1.w;        \
                *(float4*)&Bs[nxt][brow][bcol]   = b0;                         \
                *(float4*)&Bs[nxt][brow][bcol+4] = b1;                         \
            }                                                                  \
            __syncthreads();                                                   \
        }                                                                      \
    }

// ======================= 3) fused QKV projections ===========================
__global__ __launch_bounds__(256) void qkv_kernel(
    const float* __restrict__ base,
    const float* __restrict__ Wq, const float* __restrict__ Wk, const float* __restrict__ Wv,
    const float* __restrict__ bq, const float* __restrict__ bk, const float* __restrict__ bv,
    float* __restrict__ Qo, float* __restrict__ Ko, float* __restrict__ Vo)
{
    __shared__ float As[2][32][68];
    __shared__ float Bs[2][32][68];
    int which = blockIdx.z;
    const float* W    = (which == 0) ? Wq : (which == 1) ? Wk : Wv;
    const float* bias = (which == 0) ? bq : (which == 1) ? bk : bv;
    float*       C    = (which == 0) ? Qo : (which == 1) ? Ko : Vo;

    int t  = threadIdx.x;
    int tx = t & 15, ty = t >> 4;
    int row0 = blockIdx.y * 64, col0 = blockIdx.x * 64;
    const float* Atile = base + (long)row0 * 512;
    const float* Btile = W + col0;

    unsigned long long acc2[4][2] = {};
    GEMM_LOOP_NN(Atile, Btile, 512, 512, 16);

    float bv4[4];
#pragma unroll
    for (int j = 0; j < 4; j++) bv4[j] = bias[col0 + tx * 4 + j];
#pragma unroll
    for (int ii = 0; ii < 4; ii++) {
        float2 e0 = upk2(acc2[ii][0]);
        float2 e1 = upk2(acc2[ii][1]);
        float4 o;
        o.x = e0.x + bv4[0]; o.y = e0.y + bv4[1];
        o.z = e1.x + bv4[2]; o.w = e1.y + bv4[3];
        *(float4*)(C + (long)(row0 + ty * 4 + ii) * 512 + col0 + tx * 4) = o;
    }
}

// ======================= generic strided-batched SGEMM (NN) =================
__global__ __launch_bounds__(256) void sgemm_nn(
    const float* __restrict__ A, const float* __restrict__ B,
    const float* __restrict__ bias, float* __restrict__ C,
    int K, int lda, int ldb, int ldc, int bdiv,
    long sA1, long sA2, long sB1, long sB2, long sC1, long sC2)
{
    __shared__ float As[2][32][68];
    __shared__ float Bs[2][32][68];
    int bz = blockIdx.z;
    A += (long)(bz / bdiv) * sA1 + (long)(bz % bdiv) * sA2;
    B += (long)(bz / bdiv) * sB1 + (long)(bz % bdiv) * sB2;
    C += (long)(bz / bdiv) * sC1 + (long)(bz % bdiv) * sC2;

    int t  = threadIdx.x;
    int tx = t & 15, ty = t >> 4;
    int row0 = blockIdx.y * 64, col0 = blockIdx.x * 64;
    const float* Atile = A + (long)row0 * lda;
    const float* Btile = B + col0;
    int NC = K >> 5;

    unsigned long long acc2[4][2] = {};
    GEMM_LOOP_NN(Atile, Btile, lda, ldb, NC);

    float bv4[4] = {0.f, 0.f, 0.f, 0.f};
    if (bias) {
#pragma unroll
        for (int j = 0; j < 4; j++) bv4[j] = bias[col0 + tx * 4 + j];
    }
#pragma unroll
    for (int ii = 0; ii < 4; ii++) {
        float2 e0 = upk2(acc2[ii][0]);
        float2 e1 = upk2(acc2[ii][1]);
        float4 o;
        o.x = e0.x + bv4[0]; o.y = e0.y + bv4[1];
        o.z = e1.x + bv4[2]; o.w = e1.y + bv4[3];
        *(float4*)(C + (long)(row0 + ty * 4 + ii) * ldc + col0 + tx * 4) = o;
    }
}

// ======================= 4) scores = QK^T/8 - lambda*hol (NT) ===============
__global__ __launch_bounds__(256) void scores_kernel(
    const float* __restrict__ Qm, const float* __restrict__ Km,
    const float* __restrict__ hol, const float* __restrict__ lam,
    float* __restrict__ Sout)
{
    __shared__ float As[2][32][68];
    __shared__ float Bs[2][32][68];
    int zh = blockIdx.z, z = zh >> 3, h = zh & 7;
    int t  = threadIdx.x;
    int tx = t & 15, ty = t >> 4;
    int i0 = blockIdx.y * 64, j0 = blockIdx.x * 64;
    const float* Atile = Qm + (long)z * 131072 + h * 64 + (long)i0 * 512;
    const float* Btile = Km + (long)z * 131072 + h * 64 + (long)j0 * 512;

    int arow = t >> 2, acol = (t & 3) * 8;
    unsigned long long acc2[4][2] = {};

    // preload chunk 0 (K = 64 -> 2 chunks)
    float4 a0 = *(const float4*)(Atile + (long)arow * 512 + acol);
    float4 a1 = *(const float4*)(Atile + (long)arow * 512 + acol + 4);
    float4 b0 = *(const float4*)(Btile + (long)arow * 512 + acol);
    float4 b1 = *(const float4*)(Btile + (long)arow * 512 + acol + 4);
    As[0][acol+0][arow]=a0.x; As[0][acol+1][arow]=a0.y;
    As[0][acol+2][arow]=a0.z; As[0][acol+3][arow]=a0.w;
    As[0][acol+4][arow]=a1.x; As[0][acol+5][arow]=a1.y;
    As[0][acol+6][arow]=a1.z; As[0][acol+7][arow]=a1.w;
    Bs[0][acol+0][arow]=b0.x; Bs[0][acol+1][arow]=b0.y;
    Bs[0][acol+2][arow]=b0.z; Bs[0][acol+3][arow]=b0.w;
    Bs[0][acol+4][arow]=b1.x; Bs[0][acol+5][arow]=b1.y;
    Bs[0][acol+6][arow]=b1.z; Bs[0][acol+7][arow]=b1.w;
    __syncthreads();
    for (int c = 0; c < 2; c++) {
        int cur = c & 1;
        if (c == 0) {
            a0 = *(const float4*)(Atile + (long)arow * 512 + 32 + acol);
            a1 = *(const float4*)(Atile + (long)arow * 512 + 32 + acol + 4);
            b0 = *(const float4*)(Btile + (long)arow * 512 + 32 + acol);
            b1 = *(const float4*)(Btile + (long)arow * 512 + 32 + acol + 4);
        }
        GEMM_INNER_F32X2(cur)
        if (c == 0) {
            As[1][acol+0][arow]=a0.x; As[1][acol+1][arow]=a0.y;
            As[1][acol+2][arow]=a0.z; As[1][acol+3][arow]=a0.w;
            As[1][acol+4][arow]=a1.x; As[1][acol+5][arow]=a1.y;
            As[1][acol+6][arow]=a1.z; As[1][acol+7][arow]=a1.w;
            Bs[1][acol+0][arow]=b0.x; Bs[1][acol+1][arow]=b0.y;
            Bs[1][acol+2][arow]=b0.z; Bs[1][acol+3][arow]=b0.w;
            Bs[1][acol+4][arow]=b1.x; Bs[1][acol+5][arow]=b1.y;
            Bs[1][acol+6][arow]=b1.z; Bs[1][acol+7][arow]=b1.w;
        }
        __syncthreads();
    }

    float l = __ldg(lam);
#pragma unroll
    for (int ii = 0; ii < 4; ii++) {
        int irow = i0 + ty * 4 + ii;
        float2 e0 = upk2(acc2[ii][0]);
        float2 e1 = upk2(acc2[ii][1]);
        float vv[4] = {e0.x, e0.y, e1.x, e1.y};
#pragma unroll
        for (int jj = 0; jj < 4; jj++) {
            int jcol = j0 + tx * 4 + jj;
            float v = vv[jj] * 0.125f
                    - l * hol[((size_t)(z * 256 + irow)) * 256 + jcol];
            Sout[(size_t)zh * 65536 + (size_t)irow * 256 + jcol] = v;
        }
    }
}

// ======================= 5) softmax + hol partials ==========================
__global__ __launch_bounds__(256) void softmax_kernel(
    float* __restrict__ Sm, const float* __restrict__ hol,
    float* __restrict__ rowpart)
{
    __shared__ float red[8];
    __shared__ float bval;
    int row = blockIdx.x;
    int z = row >> 11;
    int i = row & 255;
    int t = threadIdx.x;
    int w = t >> 5, lane = t & 31;

    float v = Sm[(size_t)row * 256 + t];
    float m = v;
#pragma unroll
    for (int o = 16; o; o >>= 1) m = fmaxf(m, __shfl_xor_sync(0xffffffffu, m, o));
    if (lane == 0) red[w] = m;
    __syncthreads();
    if (t == 0) {
        float mm = red[0];
#pragma unroll
        for (int q = 1; q < 8; q++) mm = fmaxf(mm, red[q]);
        bval = mm;
    }
    __syncthreads();
    float e  = expf(v - bval);
    float ss = e;
#pragma unroll
    for (int o = 16; o; o >>= 1) ss += __shfl_xor_sync(0xffffffffu, ss, o);
    __syncthreads();
    if (lane == 0) red[w] = ss;
    __syncthreads();
    if (t == 0) {
        float s2 = 0.f;
#pragma unroll
        for (int q = 0; q < 8; q++) s2 += red[q];
        bval = s2;
    }
    __syncthreads();
    float at = e / bval;
    Sm[(size_t)row * 256 + t] = at;

    float hp = at * hol[((size_t)(z * 256 + i)) * 256 + t];
#pragma unroll
    for (int o = 16; o; o >>= 1) hp += __shfl_xor_sync(0xffffffffu, hp, o);
    __syncthreads();
    if (lane == 0) red[w] = hp;
    __syncthreads();
    if (t == 0) {
        float s3 = 0.f;
#pragma unroll
        for (int q = 0; q < 8; q++) s3 += red[q];
        rowpart[row] = s3;
    }
}

// ======================= 8) head-average of attn ============================
__global__ __launch_bounds__(256) void avg_kernel(
    const float* __restrict__ attn, float* __restrict__ avg)
{
    size_t idx = (size_t)blockIdx.x * 256 + threadIdx.x;
    size_t z  = idx >> 16;
    size_t ij = idx & 65535;
    float s = 0.f;
#pragma unroll
    for (int h = 0; h < 8; h++) s += attn[(z * 8 + h) * 65536 + ij];
    avg[idx] = s * 0.125f;
}

// ======================= 10) Newton-Schulz polar factor =====================
__global__ __launch_bounds__(1024) void ns_kernel(
    const float* __restrict__ Fin, float* __restrict__ Fout)
{
    __shared__ float X[32][33], Sm[32][33];
    __shared__ float wred[32];
    __shared__ float s_scale;
    __shared__ int   s_flag;
    int zi = blockIdx.x;
    int t  = threadIdx.x;
    int a = t >> 5, b = t & 31, lane = t & 31, w = t >> 5;

    float v  = Fin[(size_t)zi * 1024 + t];
    float sq = v * v;
#pragma unroll
    for (int o = 16; o; o >>= 1) sq += __shfl_xor_sync(0xffffffffu, sq, o);
    if (lane == 0) wred[w] = sq;
    __syncthreads();
    if (t == 0) {
        float s = 0.f;
#pragma unroll
        for (int q = 0; q < 32; q++) s += wred[q];
        s_scale = rsqrtf(fmaxf(s, 1e-30f));
    }
    __syncthreads();
    X[a][b] = v * s_scale;
    __syncthreads();

    for (int iter = 0; iter < 64; iter++) {
        float s = 0.f;
#pragma unroll
        for (int k = 0; k < 32; k++) s += X[k][a] * X[k][b];
        bool bad = fabsf(s - ((a == b) ? 1.f : 0.f)) > 2e-5f;
        __syncthreads();
        Sm[a][b] = s;
        if (t == 0) s_flag = 0;
        __syncthreads();
        if (bad) s_flag = 1;
        __syncthreads();
        if (!s_flag) break;
        float y = 0.f;
#pragma unroll
        for (int k = 0; k < 32; k++) y += X[a][k] * Sm[k][b];
        y = 1.5f * X[a][b] - 0.5f * y;
        __syncthreads();
        X[a][b] = y;
        __syncthreads();
    }
    Fout[(size_t)zi * 1024 + t] = X[a][b];
}

// ======================= 11) total_hol reduction ============================
__global__ __launch_bounds__(1024) void total_kernel(
    const float* __restrict__ rowpart, float* __restrict__ outv)
{
    __shared__ float wred[32];
    int t = threadIdx.x, lane = t & 31, w = t >> 5;
    float s = rowpart[t] + rowpart[t + 1024] + rowpart[t + 2048] + rowpart[t + 3072];
#pragma unroll
    for (int o = 16; o; o >>= 1) s += __shfl_xor_sync(0xffffffffu, s, o);
    if (lane == 0) wred[w] = s;
    __syncthreads();
    if (t == 0) {
        float tot = 0.f;
#pragma unroll
        for (int q = 0; q < 32; q++) tot += wred[q];
        *outv = tot;
    }
}

// ======================= launcher ===========================================
extern "C" void kernel_launch(void* const* d_in, const int* in_sizes, int n_in,
                              void* d_out, int out_size)
{
    const float* base  = (const float*)d_in[0];
    const float* fiber = (const float*)d_in[1];
    const float* conn  = (const float*)d_in[2];
    const float* gen   = (const float*)d_in[3];
    const float* Wq    = (const float*)d_in[4];
    const float* bq    = (const float*)d_in[5];
    const float* Wk    = (const float*)d_in[6];
    const float* bk    = (const float*)d_in[7];
    const float* Wv    = (const float*)d_in[8];
    const float* bv    = (const float*)d_in[9];
    const float* Wo    = (const float*)d_in[10];
    const float* bo    = (const float*)d_in[11];
    const float* lam   = (const float*)d_in[12];
    float* out = (float*)d_out;

    float* sc;
    cudaGetSymbolAddress((void**)&sc, g_scratch);
    float* M       = sc;
    float* hol     = M + 524288;
    float* Q       = hol + 131072;
    float* Km      = Q + 262144;
    float* V       = Km + 262144;
    float* attn    = V + 262144;
    float* avg     = attn + 1048576;
    float* outpre  = avg + 131072;
    float* fpre    = outpre + 262144;
    float* rowpart = fpre + 524288;

    // 1) expm + M
    expm_kernel<<<512, 1024>>>(conn, gen, M);

    // 2) holonomy (triangular grid: 8320 tiles per batch)
    hol_kernel<<<dim3(8320, 2), 128>>>(M, hol);

    // 3) fused Q/K/V projections (192 CTAs)
    qkv_kernel<<<dim3(8, 8, 3), 256>>>(base, Wq, Wk, Wv, bq, bk, bv, Q, Km, V);

    // 4) scores (fused scale + hol bias)
    scores_kernel<<<dim3(4, 4, 16), 256>>>(Q, Km, hol, lam, attn);

    // 5) softmax (+ total_hol row partials)
    softmax_kernel<<<4096, 256>>>(attn, hol, rowpart);

    // 6) attn @ V  -> outpre
    sgemm_nn<<<dim3(1, 4, 16), 256>>>(attn, V, nullptr, outpre,
                                      256, 256, 512, 512, 8,
                                      524288, 65536, 131072, 64, 131072, 64);

    // 7) @ Wo + bo -> out
    sgemm_nn<<<dim3(8, 8, 1), 256>>>(outpre, Wo, bo, out, 512, 512, 512, 512, 1, 0, 0, 0, 0, 0, 0);

    // 8) avg over heads
    avg_kernel<<<512, 256>>>(attn, avg);

    // 9) avg_attn @ fiber -> fpre
    sgemm_nn<<<dim3(16, 4, 2), 256>>>(avg, fiber, nullptr, fpre,
                                      256, 256, 1024, 1024, 1,
                                      65536, 0, 262144, 0, 262144, 0);

    // 10) polar projection -> new_fiber
    ns_kernel<<<512, 1024>>>(fpre, out + 262144);

    // 11) total_hol
    total_kernel<<<1, 1024>>>(rowpart, out + 786432);
}

// round 5
// speedup vs baseline: 1.8092x; 1.8092x over previous
#include <cuda_runtime.h>
#include <cuda_bf16.h>

// ---------------------------------------------------------------------------
// ParallelTransportAttention  (B=2, S=256, D=512, H=8, Dh=64, df=32, rank=8)
// Round 5: warp-tiled 32x32x32 matmul (4x8 reg tile, f32x2) for expm/hol/ns;
//          warp-autonomous expm & Newton-Schulz (no block barriers)
// ---------------------------------------------------------------------------

__device__ __align__(256) float g_scratch[3411968];

#define PAD 36

// ---------------- packed f32x2 helpers --------------------------------------
__device__ __forceinline__ unsigned long long pk2(float x, float y) {
    unsigned long long r;
    asm("mov.b64 %0, {%1,%2};" : "=l"(r) : "f"(x), "f"(y));
    return r;
}
__device__ __forceinline__ void fma2(unsigned long long& d,
                                     unsigned long long a, unsigned long long b) {
    asm("fma.rn.f32x2 %0, %1, %2, %0;" : "+l"(d) : "l"(a), "l"(b));
}
__device__ __forceinline__ float2 upk2(unsigned long long v) {
    float2 f;
    asm("mov.b64 {%0,%1}, %2;" : "=f"(f.x), "=f"(f.y) : "l"(v));
    return f;
}

// ---------------- warp-tiled 32x32x32 matmuls -------------------------------
// lane = rg*4+cg ; rg=lane>>2 (rows 4rg..4rg+3), cg=lane&3 (cols 8cg..8cg+7)
// acc[d][e] packs C[4rg+d][8cg+2e .. +1]

// C = A^T-style access: a-frag = A[k][4rg..] (use when A symmetric or computing A^T B)
__device__ __forceinline__ void wtile_tn(const float (*A)[PAD], const float (*B)[PAD],
                                         unsigned long long acc[4][4], int rg, int cg) {
#pragma unroll
    for (int k = 0; k < 32; k++) {
        float4 av = *(const float4*)&A[k][4 * rg];
        ulonglong2 b01 = *(const ulonglong2*)&B[k][8 * cg];
        ulonglong2 b23 = *(const ulonglong2*)&B[k][8 * cg + 4];
        unsigned long long a0 = pk2(av.x, av.x);
        unsigned long long a1 = pk2(av.y, av.y);
        unsigned long long a2 = pk2(av.z, av.z);
        unsigned long long a3 = pk2(av.w, av.w);
        fma2(acc[0][0], a0, b01.x); fma2(acc[0][1], a0, b01.y);
        fma2(acc[0][2], a0, b23.x); fma2(acc[0][3], a0, b23.y);
        fma2(acc[1][0], a1, b01.x); fma2(acc[1][1], a1, b01.y);
        fma2(acc[1][2], a1, b23.x); fma2(acc[1][3], a1, b23.y);
        fma2(acc[2][0], a2, b01.x); fma2(acc[2][1], a2, b01.y);
        fma2(acc[2][2], a2, b23.x); fma2(acc[2][3], a2, b23.y);
        fma2(acc[3][0], a3, b01.x); fma2(acc[3][1], a3, b01.y);
        fma2(acc[3][2], a3, b23.x); fma2(acc[3][3], a3, b23.y);
    }
}

// C = A @ B (row access of A)
__device__ __forceinline__ void wtile_nn(const float (*A)[PAD], const float (*B)[PAD],
                                         unsigned long long acc[4][4], int rg, int cg) {
#pragma unroll
    for (int k0 = 0; k0 < 32; k0 += 4) {
        float4 ar0 = *(const float4*)&A[4 * rg + 0][k0];
        float4 ar1 = *(const float4*)&A[4 * rg + 1][k0];
        float4 ar2 = *(const float4*)&A[4 * rg + 2][k0];
        float4 ar3 = *(const float4*)&A[4 * rg + 3][k0];
        const float* a0f = (const float*)&ar0;
        const float* a1f = (const float*)&ar1;
        const float* a2f = (const float*)&ar2;
        const float* a3f = (const float*)&ar3;
#pragma unroll
        for (int kk = 0; kk < 4; kk++) {
            ulonglong2 b01 = *(const ulonglong2*)&B[k0 + kk][8 * cg];
            ulonglong2 b23 = *(const ulonglong2*)&B[k0 + kk][8 * cg + 4];
            unsigned long long a0 = pk2(a0f[kk], a0f[kk]);
            unsigned long long a1 = pk2(a1f[kk], a1f[kk]);
            unsigned long long a2 = pk2(a2f[kk], a2f[kk]);
            unsigned long long a3 = pk2(a3f[kk], a3f[kk]);
            fma2(acc[0][0], a0, b01.x); fma2(acc[0][1], a0, b01.y);
            fma2(acc[0][2], a0, b23.x); fma2(acc[0][3], a0, b23.y);
            fma2(acc[1][0], a1, b01.x); fma2(acc[1][1], a1, b01.y);
            fma2(acc[1][2], a1, b23.x); fma2(acc[1][3], a1, b23.y);
            fma2(acc[2][0], a2, b01.x); fma2(acc[2][1], a2, b01.y);
            fma2(acc[2][2], a2, b23.x); fma2(acc[2][3], a2, b23.y);
            fma2(acc[3][0], a3, b01.x); fma2(acc[3][1], a3, b01.y);
            fma2(acc[3][2], a3, b23.x); fma2(acc[3][3], a3, b23.y);
        }
    }
}

__device__ __forceinline__ void wtile_store(float (*C)[PAD],
                                            const unsigned long long acc[4][4],
                                            int rg, int cg) {
#pragma unroll
    for (int d = 0; d < 4; d++) {
        ulonglong2 v0; v0.x = acc[d][0]; v0.y = acc[d][1];
        ulonglong2 v1; v1.x = acc[d][2]; v1.y = acc[d][3];
        *(ulonglong2*)&C[4 * rg + d][8 * cg]     = v0;
        *(ulonglong2*)&C[4 * rg + d][8 * cg + 4] = v1;
    }
}

// ======================= 1) expm + M (warp-per-matrix) ======================
// 2 warps per block (smem limit). Each warp: A = 0.1*sum c_r G_r, scale 2^-s,
// Taylor to A^9 (T kept in registers), square s times, M = T^T T.
__global__ __launch_bounds__(64) void expm_kernel(
    const float* __restrict__ conn, const float* __restrict__ gen,
    float* __restrict__ Mout)
{
    __shared__ float sA[2][32][PAD], sP[2][32][PAD], sT[2][32][PAD];
    int t = threadIdx.x;
    int w = t >> 5, lane = t & 31;
    int rg = lane >> 2, cg = lane & 3;
    int zs = blockIdx.x * 2 + w;

    float c8[8];
#pragma unroll
    for (int r = 0; r < 8; r++) c8[r] = conn[zs * 8 + r];

    // A tile: rows 4rg..4rg+3, cols 8cg..8cg+7  (2 float4 halves)
    float atile[4][8];
#pragma unroll
    for (int d = 0; d < 4; d++) {
        int row = 4 * rg + d;
#pragma unroll
        for (int h = 0; h < 2; h++) {
            float4 v = make_float4(0.f, 0.f, 0.f, 0.f);
#pragma unroll
            for (int r = 0; r < 8; r++) {
                float4 g = *(const float4*)(gen + r * 1024 + row * 32 + 8 * cg + 4 * h);
                v.x += c8[r] * g.x; v.y += c8[r] * g.y;
                v.z += c8[r] * g.z; v.w += c8[r] * g.w;
            }
            atile[d][4*h+0] = v.x * 0.1f; atile[d][4*h+1] = v.y * 0.1f;
            atile[d][4*h+2] = v.z * 0.1f; atile[d][4*h+3] = v.w * 0.1f;
        }
#pragma unroll
        for (int e = 0; e < 8; e++) sA[w][row][8 * cg + e] = atile[d][e];
    }
    __syncwarp();

    // 1-norm: lane handles column `lane`
    float cs = 0.f;
#pragma unroll
    for (int a = 0; a < 32; a++) cs += fabsf(sA[w][a][lane]);
    float nrm = cs;
#pragma unroll
    for (int o = 16; o; o >>= 1) nrm = fmaxf(nrm, __shfl_xor_sync(0xffffffffu, nrm, o));
    int s = 0;
    while (nrm > 0.25f * ldexpf(1.f, s) && s < 12) s++;
    float sc = ldexpf(1.f, -s);

    // scale A ; init P = A ; T = I + A  (T kept in regs)
    float treg[4][8];
#pragma unroll
    for (int d = 0; d < 4; d++) {
        int row = 4 * rg + d;
#pragma unroll
        for (int e = 0; e < 8; e++) {
            float a = atile[d][e] * sc;
            sA[w][row][8 * cg + e] = a;
            sP[w][row][8 * cg + e] = a;
            treg[d][e] = a + ((row == 8 * cg + e) ? 1.f : 0.f);
        }
    }
    __syncwarp();

    // Taylor terms k = 2..9
    for (int k = 2; k <= 9; k++) {
        unsigned long long acc[4][4] = {};
        wtile_nn(sP[w], sA[w], acc, rg, cg);
        float inv = 1.f / (float)k;
        __syncwarp();
#pragma unroll
        for (int d = 0; d < 4; d++) {
#pragma unroll
            for (int e = 0; e < 4; e++) {
                float2 f = upk2(acc[d][e]);
                float t0 = f.x * inv, t1 = f.y * inv;
                sP[w][4 * rg + d][8 * cg + 2 * e]     = t0;
                sP[w][4 * rg + d][8 * cg + 2 * e + 1] = t1;
                treg[d][2 * e]     += t0;
                treg[d][2 * e + 1] += t1;
            }
        }
        __syncwarp();
    }
    // T -> smem
#pragma unroll
    for (int d = 0; d < 4; d++)
#pragma unroll
        for (int e = 0; e < 8; e++)
            sT[w][4 * rg + d][8 * cg + e] = treg[d][e];
    __syncwarp();

    // squaring
    for (int it = 0; it < s; it++) {
        unsigned long long acc[4][4] = {};
        wtile_nn(sT[w], sT[w], acc, rg, cg);
        __syncwarp();
        wtile_store(sT[w], acc, rg, cg);
        __syncwarp();
    }

    // M = T^T T  -> global
    unsigned long long acc[4][4] = {};
    wtile_tn(sT[w], sT[w], acc, rg, cg);
    float* mo = Mout + (size_t)zs * 1024;
#pragma unroll
    for (int d = 0; d < 4; d++) {
        float2 f0 = upk2(acc[d][0]);
        float2 f1 = upk2(acc[d][1]);
        float2 f2 = upk2(acc[d][2]);
        float2 f3 = upk2(acc[d][3]);
        float4 o0 = make_float4(f0.x, f0.y, f1.x, f1.y);
        float4 o1 = make_float4(f2.x, f2.y, f3.x, f3.y);
        *(float4*)(mo + (4 * rg + d) * 32 + 8 * cg)     = o0;
        *(float4*)(mo + (4 * rg + d) * 32 + 8 * cg + 4) = o1;
    }
}

// ======================= 2) pairwise holonomy (warp-tiled) ==================
// block = (z, i, jt) upper-triangular tile; warp w -> j = jt*4+w.
// P = Mi @ Mj (both symmetric -> tn form, no transposes).
__global__ __launch_bounds__(128) void hol_kernel(
    const float* __restrict__ Mg, float* __restrict__ hol)
{
    __shared__ float sMi[32][PAD];
    __shared__ float sMj[4][32][PAD];
    __shared__ float sP[4][32][PAD];
    int tlin = blockIdx.x;               // 0..8319
    int z    = blockIdx.y;
    int t = threadIdx.x;
    int w = t >> 5, lane = t & 31;

    // triangular decode: C(g) = 258g - 2g^2  (float sqrt + int fixup)
    int g = (int)((258.0f - sqrtf(66564.0f - 8.0f * (float)tlin)) * 0.25f);
    g = max(0, min(63, g));
    while (258 * g - 2 * g * g > tlin) g--;
    while (258 * (g + 1) - 2 * (g + 1) * (g + 1) <= tlin) g++;
    int rem = tlin - (258 * g - 2 * g * g);
    int per = 64 - g;
    int i  = 4 * g + rem / per;
    int jt = g + rem % per;
    int j  = jt * 4 + w;

    // Mi -> smem (coop, padded rows)
    {
        const float4* mi4 = (const float4*)(Mg + (size_t)(z * 256 + i) * 1024);
        for (int fi = t; fi < 256; fi += 128) {
            float4 v = mi4[fi];
            *(float4*)&sMi[fi >> 3][(fi & 7) * 4] = v;
        }
    }
    // Mj -> smem (per warp)
    {
        const float4* mj4 = (const float4*)(Mg + (size_t)(z * 256 + j) * 1024);
        for (int fi = lane; fi < 256; fi += 32) {
            float4 v = mj4[fi];
            *(float4*)&sMj[w][fi >> 3][(fi & 7) * 4] = v;
        }
    }
    __syncthreads();

    if (j < i) return;
    if (j == i) {
        if (lane == 0) hol[((size_t)(z * 256 + i)) * 256 + i] = 0.f;
        return;
    }

    int rg = lane >> 2, cg = lane & 3;
    unsigned long long acc[4][4] = {};
    wtile_tn(sMi, sMj[w], acc, rg, cg);      // P[a][c], a=4rg+d, c=8cg..
    wtile_store(sP[w], acc, rg, cg);
    __syncwarp();

    float t1 = sP[w][lane][lane];
    float t2 = 0.f;
#pragma unroll
    for (int a = 0; a < 32; a++)
        t2 += sP[w][a][lane] * sP[w][lane][a];

#pragma unroll
    for (int off = 16; off; off >>= 1) {
        t1 += __shfl_down_sync(0xffffffffu, t1, off);
        t2 += __shfl_down_sync(0xffffffffu, t2, off);
    }
    if (lane == 0) {
        float h2 = t2 - 2.f * t1 + 32.f;
        float h  = sqrtf(fmaxf(h2, 0.f));
        hol[((size_t)(z * 256 + i)) * 256 + j] = h;
        hol[((size_t)(z * 256 + j)) * 256 + i] = h;
    }
}

// ======================= double-buffered 64x64 GEMM core (f32x2) ============
#define GEMM_INNER_F32X2(cur)                                                  \
    _Pragma("unroll")                                                          \
    for (int k = 0; k < 32; k++) {                                             \
        float4 a4 = *(const float4*)&As[cur][k][ty * 4];                       \
        ulonglong2 bu = *(const ulonglong2*)&Bs[cur][k][tx * 4];               \
        unsigned long long d0 = pk2(a4.x, a4.x);                               \
        unsigned long long d1 = pk2(a4.y, a4.y);                               \
        unsigned long long d2 = pk2(a4.z, a4.z);                               \
        unsigned long long d3 = pk2(a4.w, a4.w);                               \
        fma2(acc2[0][0], d0, bu.x); fma2(acc2[0][1], d0, bu.y);                \
        fma2(acc2[1][0], d1, bu.x); fma2(acc2[1][1], d1, bu.y);                \
        fma2(acc2[2][0], d2, bu.x); fma2(acc2[2][1], d2, bu.y);                \
        fma2(acc2[3][0], d3, bu.x); fma2(acc2[3][1], d3, bu.y);                \
    }

#define GEMM_LOOP_NN(Atile, Btile, lda, ldb, NC)                               \
    {                                                                          \
        int arow = t >> 2, acol = (t & 3) * 8;                                 \
        int brow = t >> 3, bcol = (t & 7) * 8;                                 \
        float4 a0 = *(const float4*)((Atile) + (long)arow * (lda) + acol);     \
        float4 a1 = *(const float4*)((Atile) + (long)arow * (lda) + acol + 4); \
        float4 b0 = *(const float4*)((Btile) + (long)brow * (ldb) + bcol);     \
        float4 b1 = *(const float4*)((Btile) + (long)brow * (ldb) + bcol + 4); \
        As[0][acol+0][arow]=a0.x; As[0][acol+1][arow]=a0.y;                    \
        As[0][acol+2][arow]=a0.z; As[0][acol+3][arow]=a0.w;                    \
        As[0][acol+4][arow]=a1.x; As[0][acol+5][arow]=a1.y;                    \
        As[0][acol+6][arow]=a1.z; As[0][acol+7][arow]=a1.w;                    \
        *(float4*)&Bs[0][brow][bcol]   = b0;                                   \
        *(float4*)&Bs[0][brow][bcol+4] = b1;                                   \
        __syncthreads();                                                       \
        for (int c = 0; c < (NC); c++) {                                       \
            int cur = c & 1;                                                   \
            if (c + 1 < (NC)) {                                                \
                const float* Ap = (Atile) + (c + 1) * 32;                      \
                const float* Bp = (Btile) + (long)(c + 1) * 32 * (ldb);        \
                a0 = *(const float4*)(Ap + (long)arow * (lda) + acol);         \
                a1 = *(const float4*)(Ap + (long)arow * (lda) + acol + 4);     \
                b0 = *(const float4*)(Bp + (long)brow * (ldb) + bcol);         \
                b1 = *(const float4*)(Bp + (long)brow * (ldb) + bcol + 4);     \
            }                                                                  \
            GEMM_INNER_F32X2(cur)                                              \
            if (c + 1 < (NC)) {                                                \
                int nxt = cur ^ 1;                                             \
                As[nxt][acol+0][arow]=a0.x; As[nxt][acol+1][arow]=a0.y;        \
                As[nxt][acol+2][arow]=a0.z; As[nxt][acol+3][arow]=a0.w;        \
                As[nxt][acol+4][arow]=a1.x; As[nxt][acol+5][arow]=a1.y;        \
                As[nxt][acol+6][arow]=a1.z; As[nxt][acol+7][arow]=a1.w;        \
                *(float4*)&Bs[nxt][brow][bcol]   = b0;                         \
                *(float4*)&Bs[nxt][brow][bcol+4] = b1;                         \
            }                                                                  \
            __syncthreads();                                                   \
        }                                                                      \
    }

// ======================= 3) fused QKV projections ===========================
__global__ __launch_bounds__(256) void qkv_kernel(
    const float* __restrict__ base,
    const float* __restrict__ Wq, const float* __restrict__ Wk, const float* __restrict__ Wv,
    const float* __restrict__ bq, const float* __restrict__ bk, const float* __restrict__ bv,
    float* __restrict__ Qo, float* __restrict__ Ko, float* __restrict__ Vo)
{
    __shared__ float As[2][32][68];
    __shared__ float Bs[2][32][68];
    int which = blockIdx.z;
    const float* W    = (which == 0) ? Wq : (which == 1) ? Wk : Wv;
    const float* bias = (which == 0) ? bq : (which == 1) ? bk : bv;
    float*       C    = (which == 0) ? Qo : (which == 1) ? Ko : Vo;

    int t  = threadIdx.x;
    int tx = t & 15, ty = t >> 4;
    int row0 = blockIdx.y * 64, col0 = blockIdx.x * 64;
    const float* Atile = base + (long)row0 * 512;
    const float* Btile = W + col0;

    unsigned long long acc2[4][2] = {};
    GEMM_LOOP_NN(Atile, Btile, 512, 512, 16);

    float bv4[4];
#pragma unroll
    for (int j = 0; j < 4; j++) bv4[j] = bias[col0 + tx * 4 + j];
#pragma unroll
    for (int ii = 0; ii < 4; ii++) {
        float2 e0 = upk2(acc2[ii][0]);
        float2 e1 = upk2(acc2[ii][1]);
        float4 o;
        o.x = e0.x + bv4[0]; o.y = e0.y + bv4[1];
        o.z = e1.x + bv4[2]; o.w = e1.y + bv4[3];
        *(float4*)(C + (long)(row0 + ty * 4 + ii) * 512 + col0 + tx * 4) = o;
    }
}

// ======================= generic strided-batched SGEMM (NN) =================
__global__ __launch_bounds__(256) void sgemm_nn(
    const float* __restrict__ A, const float* __restrict__ B,
    const float* __restrict__ bias, float* __restrict__ C,
    int K, int lda, int ldb, int ldc, int bdiv,
    long sA1, long sA2, long sB1, long sB2, long sC1, long sC2)
{
    __shared__ float As[2][32][68];
    __shared__ float Bs[2][32][68];
    int bz = blockIdx.z;
    A += (long)(bz / bdiv) * sA1 + (long)(bz % bdiv) * sA2;
    B += (long)(bz / bdiv) * sB1 + (long)(bz % bdiv) * sB2;
    C += (long)(bz / bdiv) * sC1 + (long)(bz % bdiv) * sC2;

    int t  = threadIdx.x;
    int tx = t & 15, ty = t >> 4;
    int row0 = blockIdx.y * 64, col0 = blockIdx.x * 64;
    const float* Atile = A + (long)row0 * lda;
    const float* Btile = B + col0;
    int NC = K >> 5;

    unsigned long long acc2[4][2] = {};
    GEMM_LOOP_NN(Atile, Btile, lda, ldb, NC);

    float bv4[4] = {0.f, 0.f, 0.f, 0.f};
    if (bias) {
#pragma unroll
        for (int j = 0; j < 4; j++) bv4[j] = bias[col0 + tx * 4 + j];
    }
#pragma unroll
    for (int ii = 0; ii < 4; ii++) {
        float2 e0 = upk2(acc2[ii][0]);
        float2 e1 = upk2(acc2[ii][1]);
        float4 o;
        o.x = e0.x + bv4[0]; o.y = e0.y + bv4[1];
        o.z = e1.x + bv4[2]; o.w = e1.y + bv4[3];
        *(float4*)(C + (long)(row0 + ty * 4 + ii) * ldc + col0 + tx * 4) = o;
    }
}

// ======================= 4) scores = QK^T/8 - lambda*hol (NT) ===============
__global__ __launch_bounds__(256) void scores_kernel(
    const float* __restrict__ Qm, const float* __restrict__ Km,
    const float* __restrict__ hol, const float* __restrict__ lam,
    float* __restrict__ Sout)
{
    __shared__ float As[2][32][68];
    __shared__ float Bs[2][32][68];
    int zh = blockIdx.z, z = zh >> 3, h = zh & 7;
    int t  = threadIdx.x;
    int tx = t & 15, ty = t >> 4;
    int i0 = blockIdx.y * 64, j0 = blockIdx.x * 64;
    const float* Atile = Qm + (long)z * 131072 + h * 64 + (long)i0 * 512;
    const float* Btile = Km + (long)z * 131072 + h * 64 + (long)j0 * 512;

    int arow = t >> 2, acol = (t & 3) * 8;
    unsigned long long acc2[4][2] = {};

    float4 a0 = *(const float4*)(Atile + (long)arow * 512 + acol);
    float4 a1 = *(const float4*)(Atile + (long)arow * 512 + acol + 4);
    float4 b0 = *(const float4*)(Btile + (long)arow * 512 + acol);
    float4 b1 = *(const float4*)(Btile + (long)arow * 512 + acol + 4);
    As[0][acol+0][arow]=a0.x; As[0][acol+1][arow]=a0.y;
    As[0][acol+2][arow]=a0.z; As[0][acol+3][arow]=a0.w;
    As[0][acol+4][arow]=a1.x; As[0][acol+5][arow]=a1.y;
    As[0][acol+6][arow]=a1.z; As[0][acol+7][arow]=a1.w;
    Bs[0][acol+0][arow]=b0.x; Bs[0][acol+1][arow]=b0.y;
    Bs[0][acol+2][arow]=b0.z; Bs[0][acol+3][arow]=b0.w;
    Bs[0][acol+4][arow]=b1.x; Bs[0][acol+5][arow]=b1.y;
    Bs[0][acol+6][arow]=b1.z; Bs[0][acol+7][arow]=b1.w;
    __syncthreads();
    for (int c = 0; c < 2; c++) {
        int cur = c & 1;
        if (c == 0) {
            a0 = *(const float4*)(Atile + (long)arow * 512 + 32 + acol);
            a1 = *(const float4*)(Atile + (long)arow * 512 + 32 + acol + 4);
            b0 = *(const float4*)(Btile + (long)arow * 512 + 32 + acol);
            b1 = *(const float4*)(Btile + (long)arow * 512 + 32 + acol + 4);
        }
        GEMM_INNER_F32X2(cur)
        if (c == 0) {
            As[1][acol+0][arow]=a0.x; As[1][acol+1][arow]=a0.y;
            As[1][acol+2][arow]=a0.z; As[1][acol+3][arow]=a0.w;
            As[1][acol+4][arow]=a1.x; As[1][acol+5][arow]=a1.y;
            As[1][acol+6][arow]=a1.z; As[1][acol+7][arow]=a1.w;
            Bs[1][acol+0][arow]=b0.x; Bs[1][acol+1][arow]=b0.y;
            Bs[1][acol+2][arow]=b0.z; Bs[1][acol+3][arow]=b0.w;
            Bs[1][acol+4][arow]=b1.x; Bs[1][acol+5][arow]=b1.y;
            Bs[1][acol+6][arow]=b1.z; Bs[1][acol+7][arow]=b1.w;
        }
        __syncthreads();
    }

    float l = __ldg(lam);
#pragma unroll
    for (int ii = 0; ii < 4; ii++) {
        int irow = i0 + ty * 4 + ii;
        float2 e0 = upk2(acc2[ii][0]);
        float2 e1 = upk2(acc2[ii][1]);
        float vv[4] = {e0.x, e0.y, e1.x, e1.y};
#pragma unroll
        for (int jj = 0; jj < 4; jj++) {
            int jcol = j0 + tx * 4 + jj;
            float v = vv[jj] * 0.125f
                    - l * hol[((size_t)(z * 256 + irow)) * 256 + jcol];
            Sout[(size_t)zh * 65536 + (size_t)irow * 256 + jcol] = v;
        }
    }
}

// ======================= 5) softmax + hol partials ==========================
__global__ __launch_bounds__(256) void softmax_kernel(
    float* __restrict__ Sm, const float* __restrict__ hol,
    float* __restrict__ rowpart)
{
    __shared__ float red[8];
    __shared__ float bval;
    int row = blockIdx.x;
    int z = row >> 11;
    int i = row & 255;
    int t = threadIdx.x;
    int w = t >> 5, lane = t & 31;

    float v = Sm[(size_t)row * 256 + t];
    float m = v;
#pragma unroll
    for (int o = 16; o; o >>= 1) m = fmaxf(m, __shfl_xor_sync(0xffffffffu, m, o));
    if (lane == 0) red[w] = m;
    __syncthreads();
    if (t == 0) {
        float mm = red[0];
#pragma unroll
        for (int q = 1; q < 8; q++) mm = fmaxf(mm, red[q]);
        bval = mm;
    }
    __syncthreads();
    float e  = expf(v - bval);
    float ss = e;
#pragma unroll
    for (int o = 16; o; o >>= 1) ss += __shfl_xor_sync(0xffffffffu, ss, o);
    __syncthreads();
    if (lane == 0) red[w] = ss;
    __syncthreads();
    if (t == 0) {
        float s2 = 0.f;
#pragma unroll
        for (int q = 0; q < 8; q++) s2 += red[q];
        bval = s2;
    }
    __syncthreads();
    float at = e / bval;
    Sm[(size_t)row * 256 + t] = at;

    float hp = at * hol[((size_t)(z * 256 + i)) * 256 + t];
#pragma unroll
    for (int o = 16; o; o >>= 1) hp += __shfl_xor_sync(0xffffffffu, hp, o);
    __syncthreads();
    if (lane == 0) red[w] = hp;
    __syncthreads();
    if (t == 0) {
        float s3 = 0.f;
#pragma unroll
        for (int q = 0; q < 8; q++) s3 += red[q];
        rowpart[row] = s3;
    }
}

// ======================= 8) head-average of attn ============================
__global__ __launch_bounds__(256) void avg_kernel(
    const float* __restrict__ attn, float* __restrict__ avg)
{
    size_t idx = (size_t)blockIdx.x * 256 + threadIdx.x;
    size_t z  = idx >> 16;
    size_t ij = idx & 65535;
    float s = 0.f;
#pragma unroll
    for (int h = 0; h < 8; h++) s += attn[(z * 8 + h) * 65536 + ij];
    avg[idx] = s * 0.125f;
}

// ======================= 10) Newton-Schulz polar (warp-per-matrix) ==========
__global__ __launch_bounds__(128) void ns_kernel(
    const float* __restrict__ Fin, float* __restrict__ Fout)
{
    __shared__ float X[4][32][PAD], S[4][32][PAD];
    int t = threadIdx.x;
    int w = t >> 5, lane = t & 31;
    int rg = lane >> 2, cg = lane & 3;
    int zi = blockIdx.x * 4 + w;

    // load + Frobenius norm
    const float4* f4 = (const float4*)(Fin + (size_t)zi * 1024);
    float4 vals[8];
    float sq = 0.f;
#pragma unroll
    for (int q = 0; q < 8; q++) {
        float4 v = f4[q * 32 + lane];
        vals[q] = v;
        sq += v.x*v.x + v.y*v.y + v.z*v.z + v.w*v.w;
    }
#pragma unroll
    for (int o = 16; o; o >>= 1) sq += __shfl_xor_sync(0xffffffffu, sq, o);
    float scale = rsqrtf(fmaxf(sq, 1e-30f));
#pragma unroll
    for (int q = 0; q < 8; q++) {
        int fi = q * 32 + lane;
        float4 v = vals[q];
        v.x *= scale; v.y *= scale; v.z *= scale; v.w *= scale;
        *(float4*)&X[w][fi >> 3][(fi & 7) * 4] = v;
    }
    __syncwarp();

    for (int iter = 0; iter < 64; iter++) {
        // S = X^T X  (tile)
        unsigned long long acc[4][4] = {};
        wtile_tn(X[w], X[w], acc, rg, cg);

        // convergence check on tile
        bool bad = false;
#pragma unroll
        for (int d = 0; d < 4; d++) {
            int a = 4 * rg + d;
#pragma unroll
            for (int e = 0; e < 4; e++) {
                float2 f = upk2(acc[d][e]);
                int b0i = 8 * cg + 2 * e, b1i = b0i + 1;
                bad |= fabsf(f.x - ((a == b0i) ? 1.f : 0.f)) > 2e-5f;
                bad |= fabsf(f.y - ((a == b1i) ? 1.f : 0.f)) > 2e-5f;
            }
        }
        if (!__any_sync(0xffffffffu, bad)) break;

        wtile_store(S[w], acc, rg, cg);
        __syncwarp();

        // Y = 1.5X - 0.5 X S  (tile into regs)
        unsigned long long acc2[4][4] = {};
        wtile_nn(X[w], S[w], acc2, rg, cg);
        float y[4][8];
#pragma unroll
        for (int d = 0; d < 4; d++) {
            int row = 4 * rg + d;
            float4 x0 = *(const float4*)&X[w][row][8 * cg];
            float4 x1 = *(const float4*)&X[w][row][8 * cg + 4];
            float2 p0 = upk2(acc2[d][0]);
            float2 p1 = upk2(acc2[d][1]);
            float2 p2 = upk2(acc2[d][2]);
            float2 p3 = upk2(acc2[d][3]);
            y[d][0] = 1.5f*x0.x - 0.5f*p0.x; y[d][1] = 1.5f*x0.y - 0.5f*p0.y;
            y[d][2] = 1.5f*x0.z - 0.5f*p1.x; y[d][3] = 1.5f*x0.w - 0.5f*p1.y;
            y[d][4] = 1.5f*x1.x - 0.5f*p2.x; y[d][5] = 1.5f*x1.y - 0.5f*p2.y;
            y[d][6] = 1.5f*x1.z - 0.5f*p3.x; y[d][7] = 1.5f*x1.w - 0.5f*p3.y;
        }
        __syncwarp();           // everyone done reading old X
#pragma unroll
        for (int d = 0; d < 4; d++) {
            int row = 4 * rg + d;
            *(float4*)&X[w][row][8 * cg]     = make_float4(y[d][0], y[d][1], y[d][2], y[d][3]);
            *(float4*)&X[w][row][8 * cg + 4] = make_float4(y[d][4], y[d][5], y[d][6], y[d][7]);
        }
        __syncwarp();
    }

    // write out
    float* fo = Fout + (size_t)zi * 1024;
#pragma unroll
    for (int q = 0; q < 8; q++) {
        int fi = q * 32 + lane;
        float4 v = *(const float4*)&X[w][fi >> 3][(fi & 7) * 4];
        *(float4*)(fo + fi * 4) = v;
    }
}

// ======================= 11) total_hol reduction ============================
__global__ __launch_bounds__(1024) void total_kernel(
    const float* __restrict__ rowpart, float* __restrict__ outv)
{
    __shared__ float wred[32];
    int t = threadIdx.x, lane = t & 31, w = t >> 5;
    float s = rowpart[t] + rowpart[t + 1024] + rowpart[t + 2048] + rowpart[t + 3072];
#pragma unroll
    for (int o = 16; o; o >>= 1) s += __shfl_xor_sync(0xffffffffu, s, o);
    if (lane == 0) wred[w] = s;
    __syncthreads();
    if (t == 0) {
        float tot = 0.f;
#pragma unroll
        for (int q = 0; q < 32; q++) tot += wred[q];
        *outv = tot;
    }
}

// ======================= launcher ===========================================
extern "C" void kernel_launch(void* const* d_in, const int* in_sizes, int n_in,
                              void* d_out, int out_size)
{
    const float* base  = (const float*)d_in[0];
    const float* fiber = (const float*)d_in[1];
    const float* conn  = (const float*)d_in[2];
    const float* gen   = (const float*)d_in[3];
    const float* Wq    = (const float*)d_in[4];
    const float* bq    = (const float*)d_in[5];
    const float* Wk    = (const float*)d_in[6];
    const float* bk    = (const float*)d_in[7];
    const float* Wv    = (const float*)d_in[8];
    const float* bv    = (const float*)d_in[9];
    const float* Wo    = (const float*)d_in[10];
    const float* bo    = (const float*)d_in[11];
    const float* lam   = (const float*)d_in[12];
    float* out = (float*)d_out;

    float* sc;
    cudaGetSymbolAddress((void**)&sc, g_scratch);
    float* M       = sc;
    float* hol     = M + 524288;
    float* Q       = hol + 131072;
    float* Km      = Q + 262144;
    float* V       = Km + 262144;
    float* attn    = V + 262144;
    float* avg     = attn + 1048576;
    float* outpre  = avg + 131072;
    float* fpre    = outpre + 262144;
    float* rowpart = fpre + 524288;

    // 1) expm + M  (warp-per-matrix, 2 warps/block)
    expm_kernel<<<256, 64>>>(conn, gen, M);

    // 2) holonomy (triangular grid)
    hol_kernel<<<dim3(8320, 2), 128>>>(M, hol);

    // 3) fused Q/K/V projections
    qkv_kernel<<<dim3(8, 8, 3), 256>>>(base, Wq, Wk, Wv, bq, bk, bv, Q, Km, V);

    // 4) scores (fused scale + hol bias)
    scores_kernel<<<dim3(4, 4, 16), 256>>>(Q, Km, hol, lam, attn);

    // 5) softmax (+ total_hol row partials)
    softmax_kernel<<<4096, 256>>>(attn, hol, rowpart);

    // 6) attn @ V  -> outpre
    sgemm_nn<<<dim3(1, 4, 16), 256>>>(attn, V, nullptr, outpre,
                                      256, 256, 512, 512, 8,
                                      524288, 65536, 131072, 64, 131072, 64);

    // 7) @ Wo + bo -> out
    sgemm_nn<<<dim3(8, 8, 1), 256>>>(outpre, Wo, bo, out, 512, 512, 512, 512, 1, 0, 0, 0, 0, 0, 0);

    // 8) avg over heads
    avg_kernel<<<512, 256>>>(attn, avg);

    // 9) avg_attn @ fiber -> fpre
    sgemm_nn<<<dim3(16, 4, 2), 256>>>(avg, fiber, nullptr, fpre,
                                      256, 256, 1024, 1024, 1,
                                      65536, 0, 262144, 0, 262144, 0);

    // 10) polar projection (warp-per-matrix NS)
    ns_kernel<<<128, 128>>>(fpre, out + 262144);

    // 11) total_hol
    total_kernel<<<1, 1024>>>(rowpart, out + 786432);
}

// round 6
// speedup vs baseline: 1.9148x; 1.0584x over previous
#include <cuda_runtime.h>
#include <cuda_bf16.h>

// ---------------------------------------------------------------------------
// ParallelTransportAttention  (B=2, S=256, D=512, H=8, Dh=64, df=32, rank=8)
// Round 6: hol smem aliasing (P over Mj) + 8-warp hol CTAs + QKV fused into
//          hol launch + tail GEMMs merged (attnV||avg, Wo||fiber)
// ---------------------------------------------------------------------------

__device__ __align__(256) float g_scratch[3411968];

#define PAD 36

// ---------------- packed f32x2 helpers --------------------------------------
__device__ __forceinline__ unsigned long long pk2(float x, float y) {
    unsigned long long r;
    asm("mov.b64 %0, {%1,%2};" : "=l"(r) : "f"(x), "f"(y));
    return r;
}
__device__ __forceinline__ void fma2(unsigned long long& d,
                                     unsigned long long a, unsigned long long b) {
    asm("fma.rn.f32x2 %0, %1, %2, %0;" : "+l"(d) : "l"(a), "l"(b));
}
__device__ __forceinline__ float2 upk2(unsigned long long v) {
    float2 f;
    asm("mov.b64 {%0,%1}, %2;" : "=f"(f.x), "=f"(f.y) : "l"(v));
    return f;
}

// ---------------- warp-tiled 32x32x32 matmuls -------------------------------
__device__ __forceinline__ void wtile_tn(const float (*A)[PAD], const float (*B)[PAD],
                                         unsigned long long acc[4][4], int rg, int cg) {
#pragma unroll
    for (int k = 0; k < 32; k++) {
        float4 av = *(const float4*)&A[k][4 * rg];
        ulonglong2 b01 = *(const ulonglong2*)&B[k][8 * cg];
        ulonglong2 b23 = *(const ulonglong2*)&B[k][8 * cg + 4];
        unsigned long long a0 = pk2(av.x, av.x);
        unsigned long long a1 = pk2(av.y, av.y);
        unsigned long long a2 = pk2(av.z, av.z);
        unsigned long long a3 = pk2(av.w, av.w);
        fma2(acc[0][0], a0, b01.x); fma2(acc[0][1], a0, b01.y);
        fma2(acc[0][2], a0, b23.x); fma2(acc[0][3], a0, b23.y);
        fma2(acc[1][0], a1, b01.x); fma2(acc[1][1], a1, b01.y);
        fma2(acc[1][2], a1, b23.x); fma2(acc[1][3], a1, b23.y);
        fma2(acc[2][0], a2, b01.x); fma2(acc[2][1], a2, b01.y);
        fma2(acc[2][2], a2, b23.x); fma2(acc[2][3], a2, b23.y);
        fma2(acc[3][0], a3, b01.x); fma2(acc[3][1], a3, b01.y);
        fma2(acc[3][2], a3, b23.x); fma2(acc[3][3], a3, b23.y);
    }
}

__device__ __forceinline__ void wtile_nn(const float (*A)[PAD], const float (*B)[PAD],
                                         unsigned long long acc[4][4], int rg, int cg) {
#pragma unroll
    for (int k0 = 0; k0 < 32; k0 += 4) {
        float4 ar0 = *(const float4*)&A[4 * rg + 0][k0];
        float4 ar1 = *(const float4*)&A[4 * rg + 1][k0];
        float4 ar2 = *(const float4*)&A[4 * rg + 2][k0];
        float4 ar3 = *(const float4*)&A[4 * rg + 3][k0];
        const float* a0f = (const float*)&ar0;
        const float* a1f = (const float*)&ar1;
        const float* a2f = (const float*)&ar2;
        const float* a3f = (const float*)&ar3;
#pragma unroll
        for (int kk = 0; kk < 4; kk++) {
            ulonglong2 b01 = *(const ulonglong2*)&B[k0 + kk][8 * cg];
            ulonglong2 b23 = *(const ulonglong2*)&B[k0 + kk][8 * cg + 4];
            unsigned long long a0 = pk2(a0f[kk], a0f[kk]);
            unsigned long long a1 = pk2(a1f[kk], a1f[kk]);
            unsigned long long a2 = pk2(a2f[kk], a2f[kk]);
            unsigned long long a3 = pk2(a3f[kk], a3f[kk]);
            fma2(acc[0][0], a0, b01.x); fma2(acc[0][1], a0, b01.y);
            fma2(acc[0][2], a0, b23.x); fma2(acc[0][3], a0, b23.y);
            fma2(acc[1][0], a1, b01.x); fma2(acc[1][1], a1, b01.y);
            fma2(acc[1][2], a1, b23.x); fma2(acc[1][3], a1, b23.y);
            fma2(acc[2][0], a2, b01.x); fma2(acc[2][1], a2, b01.y);
            fma2(acc[2][2], a2, b23.x); fma2(acc[2][3], a2, b23.y);
            fma2(acc[3][0], a3, b01.x); fma2(acc[3][1], a3, b01.y);
            fma2(acc[3][2], a3, b23.x); fma2(acc[3][3], a3, b23.y);
        }
    }
}

__device__ __forceinline__ void wtile_store(float (*C)[PAD],
                                            const unsigned long long acc[4][4],
                                            int rg, int cg) {
#pragma unroll
    for (int d = 0; d < 4; d++) {
        ulonglong2 v0; v0.x = acc[d][0]; v0.y = acc[d][1];
        ulonglong2 v1; v1.x = acc[d][2]; v1.y = acc[d][3];
        *(ulonglong2*)&C[4 * rg + d][8 * cg]     = v0;
        *(ulonglong2*)&C[4 * rg + d][8 * cg + 4] = v1;
    }
}

// ================= double-buffered 64x64 GEMM tile (device fn) ==============
// 256 threads. C[row0:+64, col0:+64] = A@B (+bias). K multiple of 32.
__device__ __forceinline__ void gemm_tile(
    const float* __restrict__ A, const float* __restrict__ B,
    const float* __restrict__ bias, float* __restrict__ C,
    int K, int lda, int ldb, int ldc, int row0, int col0,
    float (*As)[32][68], float (*Bs)[32][68])
{
    int t  = threadIdx.x;
    int tx = t & 15, ty = t >> 4;
    const float* Atile = A + (long)row0 * lda;
    const float* Btile = B + col0;
    int NC = K >> 5;

    unsigned long long acc2[4][2] = {};
    int arow = t >> 2, acol = (t & 3) * 8;
    int brow = t >> 3, bcol = (t & 7) * 8;

    float4 a0 = *(const float4*)(Atile + (long)arow * lda + acol);
    float4 a1 = *(const float4*)(Atile + (long)arow * lda + acol + 4);
    float4 b0 = *(const float4*)(Btile + (long)brow * ldb + bcol);
    float4 b1 = *(const float4*)(Btile + (long)brow * ldb + bcol + 4);
    As[0][acol+0][arow]=a0.x; As[0][acol+1][arow]=a0.y;
    As[0][acol+2][arow]=a0.z; As[0][acol+3][arow]=a0.w;
    As[0][acol+4][arow]=a1.x; As[0][acol+5][arow]=a1.y;
    As[0][acol+6][arow]=a1.z; As[0][acol+7][arow]=a1.w;
    *(float4*)&Bs[0][brow][bcol]   = b0;
    *(float4*)&Bs[0][brow][bcol+4] = b1;
    __syncthreads();
    for (int c = 0; c < NC; c++) {
        int cur = c & 1;
        if (c + 1 < NC) {
            const float* Ap = Atile + (c + 1) * 32;
            const float* Bp = Btile + (long)(c + 1) * 32 * ldb;
            a0 = *(const float4*)(Ap + (long)arow * lda + acol);
            a1 = *(const float4*)(Ap + (long)arow * lda + acol + 4);
            b0 = *(const float4*)(Bp + (long)brow * ldb + bcol);
            b1 = *(const float4*)(Bp + (long)brow * ldb + bcol + 4);
        }
#pragma unroll
        for (int k = 0; k < 32; k++) {
            float4 a4 = *(const float4*)&As[cur][k][ty * 4];
            ulonglong2 bu = *(const ulonglong2*)&Bs[cur][k][tx * 4];
            unsigned long long d0 = pk2(a4.x, a4.x);
            unsigned long long d1 = pk2(a4.y, a4.y);
            unsigned long long d2 = pk2(a4.z, a4.z);
            unsigned long long d3 = pk2(a4.w, a4.w);
            fma2(acc2[0][0], d0, bu.x); fma2(acc2[0][1], d0, bu.y);
            fma2(acc2[1][0], d1, bu.x); fma2(acc2[1][1], d1, bu.y);
            fma2(acc2[2][0], d2, bu.x); fma2(acc2[2][1], d2, bu.y);
            fma2(acc2[3][0], d3, bu.x); fma2(acc2[3][1], d3, bu.y);
        }
        if (c + 1 < NC) {
            int nxt = cur ^ 1;
            As[nxt][acol+0][arow]=a0.x; As[nxt][acol+1][arow]=a0.y;
            As[nxt][acol+2][arow]=a0.z; As[nxt][acol+3][arow]=a0.w;
            As[nxt][acol+4][arow]=a1.x; As[nxt][acol+5][arow]=a1.y;
            As[nxt][acol+6][arow]=a1.z; As[nxt][acol+7][arow]=a1.w;
            *(float4*)&Bs[nxt][brow][bcol]   = b0;
            *(float4*)&Bs[nxt][brow][bcol+4] = b1;
        }
        __syncthreads();
    }

    float bv4[4] = {0.f, 0.f, 0.f, 0.f};
    if (bias) {
#pragma unroll
        for (int j = 0; j < 4; j++) bv4[j] = bias[col0 + tx * 4 + j];
    }
#pragma unroll
    for (int ii = 0; ii < 4; ii++) {
        float2 e0 = upk2(acc2[ii][0]);
        float2 e1 = upk2(acc2[ii][1]);
        float4 o;
        o.x = e0.x + bv4[0]; o.y = e0.y + bv4[1];
        o.z = e1.x + bv4[2]; o.w = e1.y + bv4[3];
        *(float4*)(C + (long)(row0 + ty * 4 + ii) * ldc + col0 + tx * 4) = o;
    }
}

// ======================= 1) expm + M (warp-per-matrix) ======================
__global__ __launch_bounds__(64) void expm_kernel(
    const float* __restrict__ conn, const float* __restrict__ gen,
    float* __restrict__ Mout)
{
    __shared__ float sA[2][32][PAD], sP[2][32][PAD], sT[2][32][PAD];
    int t = threadIdx.x;
    int w = t >> 5, lane = t & 31;
    int rg = lane >> 2, cg = lane & 3;
    int zs = blockIdx.x * 2 + w;

    float c8[8];
#pragma unroll
    for (int r = 0; r < 8; r++) c8[r] = conn[zs * 8 + r];

    float atile[4][8];
#pragma unroll
    for (int d = 0; d < 4; d++) {
        int row = 4 * rg + d;
#pragma unroll
        for (int h = 0; h < 2; h++) {
            float4 v = make_float4(0.f, 0.f, 0.f, 0.f);
#pragma unroll
            for (int r = 0; r < 8; r++) {
                float4 g = *(const float4*)(gen + r * 1024 + row * 32 + 8 * cg + 4 * h);
                v.x += c8[r] * g.x; v.y += c8[r] * g.y;
                v.z += c8[r] * g.z; v.w += c8[r] * g.w;
            }
            atile[d][4*h+0] = v.x * 0.1f; atile[d][4*h+1] = v.y * 0.1f;
            atile[d][4*h+2] = v.z * 0.1f; atile[d][4*h+3] = v.w * 0.1f;
        }
#pragma unroll
        for (int e = 0; e < 8; e++) sA[w][row][8 * cg + e] = atile[d][e];
    }
    __syncwarp();

    float cs = 0.f;
#pragma unroll
    for (int a = 0; a < 32; a++) cs += fabsf(sA[w][a][lane]);
    float nrm = cs;
#pragma unroll
    for (int o = 16; o; o >>= 1) nrm = fmaxf(nrm, __shfl_xor_sync(0xffffffffu, nrm, o));
    int s = 0;
    while (nrm > 0.25f * ldexpf(1.f, s) && s < 12) s++;
    float sc = ldexpf(1.f, -s);

    float treg[4][8];
#pragma unroll
    for (int d = 0; d < 4; d++) {
        int row = 4 * rg + d;
#pragma unroll
        for (int e = 0; e < 8; e++) {
            float a = atile[d][e] * sc;
            sA[w][row][8 * cg + e] = a;
            sP[w][row][8 * cg + e] = a;
            treg[d][e] = a + ((row == 8 * cg + e) ? 1.f : 0.f);
        }
    }
    __syncwarp();

    for (int k = 2; k <= 9; k++) {
        unsigned long long acc[4][4] = {};
        wtile_nn(sP[w], sA[w], acc, rg, cg);
        float inv = 1.f / (float)k;
        __syncwarp();
#pragma unroll
        for (int d = 0; d < 4; d++) {
#pragma unroll
            for (int e = 0; e < 4; e++) {
                float2 f = upk2(acc[d][e]);
                float t0 = f.x * inv, t1 = f.y * inv;
                sP[w][4 * rg + d][8 * cg + 2 * e]     = t0;
                sP[w][4 * rg + d][8 * cg + 2 * e + 1] = t1;
                treg[d][2 * e]     += t0;
                treg[d][2 * e + 1] += t1;
            }
        }
        __syncwarp();
    }
#pragma unroll
    for (int d = 0; d < 4; d++)
#pragma unroll
        for (int e = 0; e < 8; e++)
            sT[w][4 * rg + d][8 * cg + e] = treg[d][e];
    __syncwarp();

    for (int it = 0; it < s; it++) {
        unsigned long long acc[4][4] = {};
        wtile_nn(sT[w], sT[w], acc, rg, cg);
        __syncwarp();
        wtile_store(sT[w], acc, rg, cg);
        __syncwarp();
    }

    unsigned long long acc[4][4] = {};
    wtile_tn(sT[w], sT[w], acc, rg, cg);
    float* mo = Mout + (size_t)zs * 1024;
#pragma unroll
    for (int d = 0; d < 4; d++) {
        float2 f0 = upk2(acc[d][0]);
        float2 f1 = upk2(acc[d][1]);
        float2 f2 = upk2(acc[d][2]);
        float2 f3 = upk2(acc[d][3]);
        float4 o0 = make_float4(f0.x, f0.y, f1.x, f1.y);
        float4 o1 = make_float4(f2.x, f2.y, f3.x, f3.y);
        *(float4*)(mo + (4 * rg + d) * 32 + 8 * cg)     = o0;
        *(float4*)(mo + (4 * rg + d) * 32 + 8 * cg + 4) = o1;
    }
}

// ============= 2+3) fused: QKV GEMMs (blocks 0..191) + holonomy =============
// hol: block = (z, i, 8-wide j tile); warp w -> j = jt*8+w; P stored over Mj.
__global__ __launch_bounds__(256) void hol_qkv_kernel(
    const float* __restrict__ Mg, float* __restrict__ hol,
    const float* __restrict__ base,
    const float* __restrict__ Wq, const float* __restrict__ Wk, const float* __restrict__ Wv,
    const float* __restrict__ bq, const float* __restrict__ bk, const float* __restrict__ bv,
    float* __restrict__ Qo, float* __restrict__ Ko, float* __restrict__ Vo)
{
    __shared__ union USm {
        struct { float sMi[32][PAD]; float sMjP[8][32][PAD]; } h;
        struct { float As[2][32][68]; float Bs[2][32][68]; } q;
    } sm;

    int x = blockIdx.x;
    if (x < 192) {
        int which = x / 64, tile = x % 64;
        const float* W    = (which == 0) ? Wq : (which == 1) ? Wk : Wv;
        const float* bias = (which == 0) ? bq : (which == 1) ? bk : bv;
        float*       C    = (which == 0) ? Qo : (which == 1) ? Ko : Vo;
        gemm_tile(base, W, bias, C, 512, 512, 512, 512,
                  (tile >> 3) * 64, (tile & 7) * 64, sm.q.As, sm.q.Bs);
        return;
    }

    int idx  = x - 192;
    int z    = idx / 4224;
    int tlin = idx % 4224;
    int t = threadIdx.x;
    int w = t >> 5, lane = t & 31;

    // decode 8-wide triangular tile: F(g) = 260g - 4g^2, per-g count 8*(32-g)
    int g = (int)((65.0f - sqrtf(4225.0f - (float)tlin)) * 0.5f);
    g = max(0, min(31, g));
    while (260 * g - 4 * g * g > tlin) g--;
    while (260 * (g + 1) - 4 * (g + 1) * (g + 1) <= tlin) g++;
    int rem = tlin - (260 * g - 4 * g * g);
    int per = 32 - g;
    int i  = 8 * g + rem / per;
    int jt = g + rem % per;
    int j  = jt * 8 + w;

    // Mi -> smem (256 threads, one float4 each)
    {
        const float4* mi4 = (const float4*)(Mg + (size_t)(z * 256 + i) * 1024);
        float4 v = mi4[t];
        *(float4*)&sm.h.sMi[t >> 3][(t & 7) * 4] = v;
    }
    // Mj -> smem (per warp)
    {
        const float4* mj4 = (const float4*)(Mg + (size_t)(z * 256 + j) * 1024);
        for (int fi = lane; fi < 256; fi += 32) {
            float4 v = mj4[fi];
            *(float4*)&sm.h.sMjP[w][fi >> 3][(fi & 7) * 4] = v;
        }
    }
    __syncthreads();

    if (j < i) return;
    if (j == i) {
        if (lane == 0) hol[((size_t)(z * 256 + i)) * 256 + i] = 0.f;
        return;
    }

    int rg = lane >> 2, cg = lane & 3;
    unsigned long long acc[4][4] = {};
    wtile_tn(sm.h.sMi, sm.h.sMjP[w], acc, rg, cg);
    __syncwarp();                            // all lanes done reading Mj
    wtile_store(sm.h.sMjP[w], acc, rg, cg);  // P overwrites Mj
    __syncwarp();

    float t1 = sm.h.sMjP[w][lane][lane];
    float t2 = 0.f;
#pragma unroll
    for (int a = 0; a < 32; a++)
        t2 += sm.h.sMjP[w][a][lane] * sm.h.sMjP[w][lane][a];

#pragma unroll
    for (int off = 16; off; off >>= 1) {
        t1 += __shfl_down_sync(0xffffffffu, t1, off);
        t2 += __shfl_down_sync(0xffffffffu, t2, off);
    }
    if (lane == 0) {
        float h2 = t2 - 2.f * t1 + 32.f;
        float h  = sqrtf(fmaxf(h2, 0.f));
        hol[((size_t)(z * 256 + i)) * 256 + j] = h;
        hol[((size_t)(z * 256 + j)) * 256 + i] = h;
    }
}

// ======================= 4) scores = QK^T/8 - lambda*hol (NT) ===============
__global__ __launch_bounds__(256) void scores_kernel(
    const float* __restrict__ Qm, const float* __restrict__ Km,
    const float* __restrict__ hol, const float* __restrict__ lam,
    float* __restrict__ Sout)
{
    __shared__ float As[2][32][68];
    __shared__ float Bs[2][32][68];
    int zh = blockIdx.z, z = zh >> 3, h = zh & 7;
    int t  = threadIdx.x;
    int tx = t & 15, ty = t >> 4;
    int i0 = blockIdx.y * 64, j0 = blockIdx.x * 64;
    const float* Atile = Qm + (long)z * 131072 + h * 64 + (long)i0 * 512;
    const float* Btile = Km + (long)z * 131072 + h * 64 + (long)j0 * 512;

    int arow = t >> 2, acol = (t & 3) * 8;
    unsigned long long acc2[4][2] = {};

    float4 a0 = *(const float4*)(Atile + (long)arow * 512 + acol);
    float4 a1 = *(const float4*)(Atile + (long)arow * 512 + acol + 4);
    float4 b0 = *(const float4*)(Btile + (long)arow * 512 + acol);
    float4 b1 = *(const float4*)(Btile + (long)arow * 512 + acol + 4);
    As[0][acol+0][arow]=a0.x; As[0][acol+1][arow]=a0.y;
    As[0][acol+2][arow]=a0.z; As[0][acol+3][arow]=a0.w;
    As[0][acol+4][arow]=a1.x; As[0][acol+5][arow]=a1.y;
    As[0][acol+6][arow]=a1.z; As[0][acol+7][arow]=a1.w;
    Bs[0][acol+0][arow]=b0.x; Bs[0][acol+1][arow]=b0.y;
    Bs[0][acol+2][arow]=b0.z; Bs[0][acol+3][arow]=b0.w;
    Bs[0][acol+4][arow]=b1.x; Bs[0][acol+5][arow]=b1.y;
    Bs[0][acol+6][arow]=b1.z; Bs[0][acol+7][arow]=b1.w;
    __syncthreads();
    for (int c = 0; c < 2; c++) {
        int cur = c & 1;
        if (c == 0) {
            a0 = *(const float4*)(Atile + (long)arow * 512 + 32 + acol);
            a1 = *(const float4*)(Atile + (long)arow * 512 + 32 + acol + 4);
            b0 = *(const float4*)(Btile + (long)arow * 512 + 32 + acol);
            b1 = *(const float4*)(Btile + (long)arow * 512 + 32 + acol + 4);
        }
#pragma unroll
        for (int k = 0; k < 32; k++) {
            float4 a4 = *(const float4*)&As[cur][k][ty * 4];
            ulonglong2 bu = *(const ulonglong2*)&Bs[cur][k][tx * 4];
            unsigned long long d0 = pk2(a4.x, a4.x);
            unsigned long long d1 = pk2(a4.y, a4.y);
            unsigned long long d2 = pk2(a4.z, a4.z);
            unsigned long long d3 = pk2(a4.w, a4.w);
            fma2(acc2[0][0], d0, bu.x); fma2(acc2[0][1], d0, bu.y);
            fma2(acc2[1][0], d1, bu.x); fma2(acc2[1][1], d1, bu.y);
            fma2(acc2[2][0], d2, bu.x); fma2(acc2[2][1], d2, bu.y);
            fma2(acc2[3][0], d3, bu.x); fma2(acc2[3][1], d3, bu.y);
        }
        if (c == 0) {
            As[1][acol+0][arow]=a0.x; As[1][acol+1][arow]=a0.y;
            As[1][acol+2][arow]=a0.z; As[1][acol+3][arow]=a0.w;
            As[1][acol+4][arow]=a1.x; As[1][acol+5][arow]=a1.y;
            As[1][acol+6][arow]=a1.z; As[1][acol+7][arow]=a1.w;
            Bs[1][acol+0][arow]=b0.x; Bs[1][acol+1][arow]=b0.y;
            Bs[1][acol+2][arow]=b0.z; Bs[1][acol+3][arow]=b0.w;
            Bs[1][acol+4][arow]=b1.x; Bs[1][acol+5][arow]=b1.y;
            Bs[1][acol+6][arow]=b1.z; Bs[1][acol+7][arow]=b1.w;
        }
        __syncthreads();
    }

    float l = __ldg(lam);
#pragma unroll
    for (int ii = 0; ii < 4; ii++) {
        int irow = i0 + ty * 4 + ii;
        float2 e0 = upk2(acc2[ii][0]);
        float2 e1 = upk2(acc2[ii][1]);
        float vv[4] = {e0.x, e0.y, e1.x, e1.y};
#pragma unroll
        for (int jj = 0; jj < 4; jj++) {
            int jcol = j0 + tx * 4 + jj;
            float v = vv[jj] * 0.125f
                    - l * hol[((size_t)(z * 256 + irow)) * 256 + jcol];
            Sout[(size_t)zh * 65536 + (size_t)irow * 256 + jcol] = v;
        }
    }
}

// ======================= 5) softmax + hol partials ==========================
__global__ __launch_bounds__(256) void softmax_kernel(
    float* __restrict__ Sm, const float* __restrict__ hol,
    float* __restrict__ rowpart)
{
    __shared__ float red[8];
    __shared__ float bval;
    int row = blockIdx.x;
    int z = row >> 11;
    int i = row & 255;
    int t = threadIdx.x;
    int w = t >> 5, lane = t & 31;

    float v = Sm[(size_t)row * 256 + t];
    float m = v;
#pragma unroll
    for (int o = 16; o; o >>= 1) m = fmaxf(m, __shfl_xor_sync(0xffffffffu, m, o));
    if (lane == 0) red[w] = m;
    __syncthreads();
    if (t == 0) {
        float mm = red[0];
#pragma unroll
        for (int q = 1; q < 8; q++) mm = fmaxf(mm, red[q]);
        bval = mm;
    }
    __syncthreads();
    float e  = expf(v - bval);
    float ss = e;
#pragma unroll
    for (int o = 16; o; o >>= 1) ss += __shfl_xor_sync(0xffffffffu, ss, o);
    __syncthreads();
    if (lane == 0) red[w] = ss;
    __syncthreads();
    if (t == 0) {
        float s2 = 0.f;
#pragma unroll
        for (int q = 0; q < 8; q++) s2 += red[q];
        bval = s2;
    }
    __syncthreads();
    float at = e / bval;
    Sm[(size_t)row * 256 + t] = at;

    float hp = at * hol[((size_t)(z * 256 + i)) * 256 + t];
#pragma unroll
    for (int o = 16; o; o >>= 1) hp += __shfl_xor_sync(0xffffffffu, hp, o);
    __syncthreads();
    if (lane == 0) red[w] = hp;
    __syncthreads();
    if (t == 0) {
        float s3 = 0.f;
#pragma unroll
        for (int q = 0; q < 8; q++) s3 += red[q];
        rowpart[row] = s3;
    }
}

// =============== 6+8) tail1: attn@V (64 blocks) || head-avg (512) ===========
__global__ __launch_bounds__(256) void tail1_kernel(
    const float* __restrict__ attn, const float* __restrict__ V,
    float* __restrict__ outpre, float* __restrict__ avg)
{
    __shared__ float As[2][32][68];
    __shared__ float Bs[2][32][68];
    int x = blockIdx.x;
    if (x < 64) {
        int bz = x >> 2, by = x & 3;          // bz = z*8+h
        const float* A = attn + (long)bz * 65536;
        const float* B = V + (long)(bz >> 3) * 131072 + (long)(bz & 7) * 64;
        float* C = outpre + (long)(bz >> 3) * 131072 + (long)(bz & 7) * 64;
        gemm_tile(A, B, nullptr, C, 256, 256, 512, 512, by * 64, 0, As, Bs);
    } else {
        size_t idx = (size_t)(x - 64) * 256 + threadIdx.x;   // 0..131071
        size_t z  = idx >> 16;
        size_t ij = idx & 65535;
        float s = 0.f;
#pragma unroll
        for (int h = 0; h < 8; h++) s += attn[(z * 8 + h) * 65536 + ij];
        avg[idx] = s * 0.125f;
    }
}

// =============== 7+9) tail2: @Wo+bo (64 blocks) || avg@fiber (128) ==========
__global__ __launch_bounds__(256) void tail2_kernel(
    const float* __restrict__ outpre, const float* __restrict__ Wo,
    const float* __restrict__ bo, float* __restrict__ outp,
    const float* __restrict__ avg, const float* __restrict__ fiber,
    float* __restrict__ fpre)
{
    __shared__ float As[2][32][68];
    __shared__ float Bs[2][32][68];
    int x = blockIdx.x;
    if (x < 64) {
        int by = x >> 3, bx = x & 7;
        gemm_tile(outpre, Wo, bo, outp, 512, 512, 512, 512,
                  by * 64, bx * 64, As, Bs);
    } else {
        int v = x - 64;                        // 0..127
        int bz = v >> 6, r = v & 63;
        int by = r >> 4, bx = r & 15;
        gemm_tile(avg + (long)bz * 65536, fiber + (long)bz * 262144, nullptr,
                  fpre + (long)bz * 262144, 256, 256, 1024, 1024,
                  by * 64, bx * 64, As, Bs);
    }
}

// ======================= 10) Newton-Schulz polar (warp-per-matrix) ==========
__global__ __launch_bounds__(128) void ns_kernel(
    const float* __restrict__ Fin, float* __restrict__ Fout)
{
    __shared__ float X[4][32][PAD], S[4][32][PAD];
    int t = threadIdx.x;
    int w = t >> 5, lane = t & 31;
    int rg = lane >> 2, cg = lane & 3;
    int zi = blockIdx.x * 4 + w;

    const float4* f4 = (const float4*)(Fin + (size_t)zi * 1024);
    float4 vals[8];
    float sq = 0.f;
#pragma unroll
    for (int q = 0; q < 8; q++) {
        float4 v = f4[q * 32 + lane];
        vals[q] = v;
        sq += v.x*v.x + v.y*v.y + v.z*v.z + v.w*v.w;
    }
#pragma unroll
    for (int o = 16; o; o >>= 1) sq += __shfl_xor_sync(0xffffffffu, sq, o);
    float scale = rsqrtf(fmaxf(sq, 1e-30f));
#pragma unroll
    for (int q = 0; q < 8; q++) {
        int fi = q * 32 + lane;
        float4 v = vals[q];
        v.x *= scale; v.y *= scale; v.z *= scale; v.w *= scale;
        *(float4*)&X[w][fi >> 3][(fi & 7) * 4] = v;
    }
    __syncwarp();

    for (int iter = 0; iter < 64; iter++) {
        unsigned long long acc[4][4] = {};
        wtile_tn(X[w], X[w], acc, rg, cg);

        bool bad = false;
#pragma unroll
        for (int d = 0; d < 4; d++) {
            int a = 4 * rg + d;
#pragma unroll
            for (int e = 0; e < 4; e++) {
                float2 f = upk2(acc[d][e]);
                int b0i = 8 * cg + 2 * e, b1i = b0i + 1;
                bad |= fabsf(f.x - ((a == b0i) ? 1.f : 0.f)) > 2e-5f;
                bad |= fabsf(f.y - ((a == b1i) ? 1.f : 0.f)) > 2e-5f;
            }
        }
        if (!__any_sync(0xffffffffu, bad)) break;

        wtile_store(S[w], acc, rg, cg);
        __syncwarp();

        unsigned long long acc2[4][4] = {};
        wtile_nn(X[w], S[w], acc2, rg, cg);
        float y[4][8];
#pragma unroll
        for (int d = 0; d < 4; d++) {
            int row = 4 * rg + d;
            float4 x0 = *(const float4*)&X[w][row][8 * cg];
            float4 x1 = *(const float4*)&X[w][row][8 * cg + 4];
            float2 p0 = upk2(acc2[d][0]);
            float2 p1 = upk2(acc2[d][1]);
            float2 p2 = upk2(acc2[d][2]);
            float2 p3 = upk2(acc2[d][3]);
            y[d][0] = 1.5f*x0.x - 0.5f*p0.x; y[d][1] = 1.5f*x0.y - 0.5f*p0.y;
            y[d][2] = 1.5f*x0.z - 0.5f*p1.x; y[d][3] = 1.5f*x0.w - 0.5f*p1.y;
            y[d][4] = 1.5f*x1.x - 0.5f*p2.x; y[d][5] = 1.5f*x1.y - 0.5f*p2.y;
            y[d][6] = 1.5f*x1.z - 0.5f*p3.x; y[d][7] = 1.5f*x1.w - 0.5f*p3.y;
        }
        __syncwarp();
#pragma unroll
        for (int d = 0; d < 4; d++) {
            int row = 4 * rg + d;
            *(float4*)&X[w][row][8 * cg]     = make_float4(y[d][0], y[d][1], y[d][2], y[d][3]);
            *(float4*)&X[w][row][8 * cg + 4] = make_float4(y[d][4], y[d][5], y[d][6], y[d][7]);
        }
        __syncwarp();
    }

    float* fo = Fout + (size_t)zi * 1024;
#pragma unroll
    for (int q = 0; q < 8; q++) {
        int fi = q * 32 + lane;
        float4 v = *(const float4*)&X[w][fi >> 3][(fi & 7) * 4];
        *(float4*)(fo + fi * 4) = v;
    }
}

// ======================= 11) total_hol reduction ============================
__global__ __launch_bounds__(1024) void total_kernel(
    const float* __restrict__ rowpart, float* __restrict__ outv)
{
    __shared__ float wred[32];
    int t = threadIdx.x, lane = t & 31, w = t >> 5;
    float s = rowpart[t] + rowpart[t + 1024] + rowpart[t + 2048] + rowpart[t + 3072];
#pragma unroll
    for (int o = 16; o; o >>= 1) s += __shfl_xor_sync(0xffffffffu, s, o);
    if (lane == 0) wred[w] = s;
    __syncthreads();
    if (t == 0) {
        float tot = 0.f;
#pragma unroll
        for (int q = 0; q < 32; q++) tot += wred[q];
        *outv = tot;
    }
}

// ======================= launcher ===========================================
extern "C" void kernel_launch(void* const* d_in, const int* in_sizes, int n_in,
                              void* d_out, int out_size)
{
    const float* base  = (const float*)d_in[0];
    const float* fiber = (const float*)d_in[1];
    const float* conn  = (const float*)d_in[2];
    const float* gen   = (const float*)d_in[3];
    const float* Wq    = (const float*)d_in[4];
    const float* bq    = (const float*)d_in[5];
    const float* Wk    = (const float*)d_in[6];
    const float* bk    = (const float*)d_in[7];
    const float* Wv    = (const float*)d_in[8];
    const float* bv    = (const float*)d_in[9];
    const float* Wo    = (const float*)d_in[10];
    const float* bo    = (const float*)d_in[11];
    const float* lam   = (const float*)d_in[12];
    float* out = (float*)d_out;

    float* sc;
    cudaGetSymbolAddress((void**)&sc, g_scratch);
    float* M       = sc;
    float* hol     = M + 524288;
    float* Q       = hol + 131072;
    float* Km      = Q + 262144;
    float* V       = Km + 262144;
    float* attn    = V + 262144;
    float* avg     = attn + 1048576;
    float* outpre  = avg + 131072;
    float* fpre    = outpre + 262144;
    float* rowpart = fpre + 524288;

    // 1) expm + M
    expm_kernel<<<256, 64>>>(conn, gen, M);

    // 2+3) QKV (192 blocks) fused with holonomy (2*4224 blocks)
    hol_qkv_kernel<<<192 + 8448, 256>>>(M, hol, base, Wq, Wk, Wv,
                                        bq, bk, bv, Q, Km, V);

    // 4) scores
    scores_kernel<<<dim3(4, 4, 16), 256>>>(Q, Km, hol, lam, attn);

    // 5) softmax
    softmax_kernel<<<4096, 256>>>(attn, hol, rowpart);

    // 6+8) attn@V || head-average
    tail1_kernel<<<576, 256>>>(attn, V, outpre, avg);

    // 7+9) @Wo+bo || avg@fiber
    tail2_kernel<<<192, 256>>>(outpre, Wo, bo, out, avg, fiber, fpre);

    // 10) polar projection
    ns_kernel<<<128, 128>>>(fpre, out + 262144);

    // 11) total_hol
    total_kernel<<<1, 1024>>>(rowpart, out + 786432);
}